// round 16
// baseline (speedup 1.0000x reference)
#include <cuda_runtime.h>
#include <cstdint>

namespace {
constexpr int H = 64, W = 64;
constexpr int C = 384;   // 48 positions * 8 channels
constexpr int B = 32;
constexpr int AP = 72;   // smem row pitch (floats), 288B -> 16B-aligned rows
constexpr int AR = 68;   // logical rows/cols of padded+displaced tile
}

// 5-tap normalized gaussian from fractional offset sub, sigma=0.5.
__device__ __forceinline__ void gauss5(float sub, float w[5]) {
  const float c1 = 0.135335283236612692f;    // exp(-2)
  const float c2 = 3.35462627902511839e-4f;  // exp(-8)
  float t  = __expf(-4.0f * sub);
  float it = 1.0f / t;
  float e0 = c2 * it * it;
  float e1 = c1 * it;
  float e2 = 1.0f;
  float e3 = c1 * t;
  float e4 = c2 * t * t;
  float inv = 1.0f / (e0 + e1 + e2 + e3 + e4);
  w[0] = e0 * inv; w[1] = e1 * inv; w[2] = e2 * inv;
  w[3] = e3 * inv; w[4] = e4 * inv;
}

// packed f32x2 helpers (sm_103a packed fp32 pipe; PTX-only)
__device__ __forceinline__ uint64_t pack2(float lo, float hi) {
  uint64_t r;
  asm("mov.b64 %0, {%1, %2};" : "=l"(r) : "f"(lo), "f"(hi));
  return r;
}
__device__ __forceinline__ uint64_t fma2(uint64_t a, uint64_t b, uint64_t c) {
  uint64_t d;
  asm("fma.rn.f32x2 %0, %1, %2, %3;" : "=l"(d) : "l"(a), "l"(b), "l"(c));
  return d;
}
__device__ __forceinline__ void unpack2(uint64_t v, float& lo, float& hi) {
  asm("mov.b64 {%0, %1}, %2;" : "=f"(lo), "=f"(hi) : "l"(v));
}

__global__ __launch_bounds__(256, 6) void displace_gauss_kernel(
    const float* __restrict__ x, const float* __restrict__ offset,
    float* __restrict__ out) {
  __shared__ __align__(16) float A[AR * AP];
  __shared__ float swx[5], swy[5];

  const int plane = blockIdx.x;         // b*C + c
  const int c = plane % C;
  const int p = c >> 3;                 // 8 channels per position
  const int tid = threadIdx.x;

  // --- every thread computes integer offset itself (broadcast loads) ---
  const float ox = __ldg(&offset[2 * p + 0]);
  const float oy = __ldg(&offset[2 * p + 1]);
  const float rxv = rintf(ox), ryv = rintf(oy);   // matches jnp.round
  const int dx = (int)rxv;
  const int dy = (int)ryv;

  // --- Gaussian weights: lane 0 does x-axis, lane 1 does y-axis ---
  if (tid < 2) {
    float w[5];
    gauss5((tid == 0) ? (ox - rxv) : (oy - ryv), w);
    float* d = (tid == 0) ? swx : swy;
#pragma unroll
    for (int j = 0; j < 5; j++) d[j] = w[j];
  }

  // --- zero the 2-wide halo (always zero: px/py out of [0,64) there) ---
  if (tid < AR) {
    A[0 * AP + tid] = 0.f;  A[1 * AP + tid] = 0.f;
    A[66 * AP + tid] = 0.f; A[67 * AP + tid] = 0.f;
    float* row = &A[tid * AP];
    row[0] = 0.f; row[1] = 0.f; row[66] = 0.f; row[67] = 0.f;
  }

  // --- fill 64x64 interior (R5-proven __ldcs float4 path) ---
  const float* __restrict__ src = x + (size_t)plane * (H * W);
  const int fx = tid & 15;              // float4 column index 0..15
  const int fy = tid >> 4;              // row 0..15 (4 strided passes)
  const int px = fx * 4;
  float* __restrict__ dstA = &A[(2 + fy) * AP + 2 + px];

  if ((dx & 3) == 0) {
    // vector path: displaced float4 stays aligned & validity is all-or-none
    const int sx = px - dx;             // multiple of 4
    const bool sxok = (unsigned)sx <= (unsigned)(W - 4);
#pragma unroll
    for (int i = 0; i < 4; i++) {
      const int sy = fy + i * 16 - dy;
      float4 v = make_float4(0.f, 0.f, 0.f, 0.f);
      if (sxok && (unsigned)sy < (unsigned)H)
        v = __ldcs(reinterpret_cast<const float4*>(&src[sy * W + sx]));
      float* d = dstA + i * 16 * AP;    // col 2+4k: 8B-aligned -> STS.64 x2
      *reinterpret_cast<float2*>(d + 0) = make_float2(v.x, v.y);
      *reinterpret_cast<float2*>(d + 2) = make_float2(v.z, v.w);
    }
  } else {
    // generic scalar path (not taken for this problem's offset grid)
#pragma unroll
    for (int i = 0; i < 4; i++) {
      const int sy = fy + i * 16 - dy;
      const bool syok = (unsigned)sy < (unsigned)H;
#pragma unroll
      for (int u = 0; u < 4; u++) {
        const int sxu = px + u - dx;
        float v = 0.f;
        if (syok && (unsigned)sxu < (unsigned)W) v = __ldcs(&src[sy * W + sxu]);
        dstA[i * 16 * AP + u] = v;
      }
    }
  }
  __syncthreads();                      // single barrier

  // --- per-thread output tile coordinates (4 wide x 4 tall) ---
  const int txi = tid & 15;             // 16 x-tiles of width 4
  const int tyi = tid >> 4;             // 16 y-tiles of height 4
  const int x0 = txi * 4;
  const int y0 = tyi * 4;
  float* __restrict__ dst = out + (size_t)plane * (H * W);

  // --- liveness: does this tile's input window touch any valid pixel? ---
  {
    const int cx0 = dx > 0 ? dx : 0;
    const int cx1 = dx < 0 ? (W - 1 + dx) : (W - 1);
    const int cy0 = dy > 0 ? dy : 0;
    const int cy1 = dy < 0 ? (H - 1 + dy) : (H - 1);
    const bool live = (x0 + 5 >= cx0) & (x0 - 2 <= cx1) &
                      (y0 + 5 >= cy0) & (y0 - 2 <= cy1);
    if (!live) {                        // entire tile is exactly zero
      const float4 z = make_float4(0.f, 0.f, 0.f, 0.f);
#pragma unroll
      for (int o = 0; o < 4; o++)
        __stcs(reinterpret_cast<float4*>(&dst[(y0 + o) * W + x0]), z);
      return;                           // no more barriers follow
    }
  }

  // --- separable conv in packed f32x2: 2 output cols per lane-pair op ---
  uint64_t wx2[5], wy2[5];
#pragma unroll
  for (int j = 0; j < 5; j++) {
    wx2[j] = pack2(swx[j], swx[j]);
    wy2[j] = pack2(swy[j], swy[j]);
  }

  uint64_t acc01[4], acc23[4];
#pragma unroll
  for (int o = 0; o < 4; o++) { acc01[o] = 0ull; acc23[o] = 0ull; }

#pragma unroll
  for (int r = 0; r < 8; r++) {         // 8 h-rows feed 4 output rows
    const float* row = &A[(y0 + r) * AP + x0];
    float4 a0 = *reinterpret_cast<const float4*>(row);
    float4 a1 = *reinterpret_cast<const float4*>(row + 4);
    float a[8] = {a0.x, a0.y, a0.z, a0.w, a1.x, a1.y, a1.z, a1.w};
    // shifted pairs P[u] = (a[u], a[u+1]) — packs run on alu pipe
    uint64_t P[7];
#pragma unroll
    for (int u = 0; u < 7; u++) P[u] = pack2(a[u], a[u + 1]);
    // h01 = (h0,h1), h23 = (h2,h3): 10 FFMA2 instead of 20 FFMA
    uint64_t h01 = 0ull, h23 = 0ull;
#pragma unroll
    for (int j = 0; j < 5; j++) {
      h01 = fma2(wx2[j], P[j], h01);
      h23 = fma2(wx2[j], P[j + 2], h23);
    }
#pragma unroll
    for (int o = 0; o < 4; o++) {
      int i = r - o;                    // compile-time pruned
      if (i >= 0 && i < 5) {
        acc01[o] = fma2(wy2[i], h01, acc01[o]);
        acc23[o] = fma2(wy2[i], h23, acc23[o]);
      }
    }
  }

#pragma unroll
  for (int o = 0; o < 4; o++) {
    float v0, v1, v2, v3;
    unpack2(acc01[o], v0, v1);
    unpack2(acc23[o], v2, v3);
    __stcs(reinterpret_cast<float4*>(&dst[(y0 + o) * W + x0]),
           make_float4(v0, v1, v2, v3));
  }
}

extern "C" void kernel_launch(void* const* d_in, const int* in_sizes, int n_in,
                              void* d_out, int out_size) {
  const float* x = (const float*)d_in[0];
  const float* offset = (const float*)d_in[1];
  float* out = (float*)d_out;
  displace_gauss_kernel<<<B * C, 256>>>(x, offset, out);
}

// round 17
// speedup vs baseline: 1.2273x; 1.2273x over previous
#include <cuda_runtime.h>

namespace {
constexpr int H = 64, W = 64;
constexpr int C = 384;   // 48 positions * 8 channels
constexpr int B = 32;
constexpr int AP = 72;   // smem row pitch (floats), 288B -> 16B-aligned rows
constexpr int AR = 68;   // logical rows/cols of padded+displaced tile
}

__global__ __launch_bounds__(256, 6) void displace_gauss_kernel(
    const float* __restrict__ x, const float* __restrict__ offset,
    float* __restrict__ out) {
  __shared__ __align__(16) float A[AR * AP];
  __shared__ float swx[5], swy[5];

  const int plane = blockIdx.x;         // b*C + c
  const int c = plane % C;
  const int p = c >> 3;                 // 8 channels per position
  const int tid = threadIdx.x;

  // --- every thread computes integer offset itself (broadcast loads) ---
  const float ox = __ldg(&offset[2 * p + 0]);
  const float oy = __ldg(&offset[2 * p + 1]);
  const float rx = rintf(ox), ry = rintf(oy);   // matches jnp.round
  const int dx = (int)rx;
  const int dy = (int)ry;

  // --- Gaussian weights: lane 0 does x-axis, lane 1 does y-axis ---
  if (tid < 2) {
    const float sub = (tid == 0) ? (ox - rx) : (oy - ry);
    float e[5], s = 0.f;
#pragma unroll
    for (int j = 0; j < 5; j++) {
      float d = (float)(j - 2) + sub;
      e[j] = expf(-d * d * 2.0f);       // 1/(2*sigma^2) = 2 for sigma=0.5
      s += e[j];
    }
    const float inv = 1.0f / s;         // 2D norm = product of 1D norms
    float* w = (tid == 0) ? swx : swy;
#pragma unroll
    for (int j = 0; j < 5; j++) w[j] = e[j] * inv;
  }

  // --- zero the 2-wide halo (always zero: px/py out of [0,64) there) ---
  if (tid < AR) {
    A[0 * AP + tid] = 0.f;  A[1 * AP + tid] = 0.f;
    A[66 * AP + tid] = 0.f; A[67 * AP + tid] = 0.f;
    float* row = &A[tid * AP];
    row[0] = 0.f; row[1] = 0.f; row[66] = 0.f; row[67] = 0.f;
  }

  // --- fill 64x64 interior ---
  const float* __restrict__ src = x + (size_t)plane * (H * W);
  const int fx = tid & 15;              // float4 column index 0..15
  const int fy = tid >> 4;              // row 0..15 (4 strided passes)
  const int px = fx * 4;
  float* __restrict__ dstA = &A[(2 + fy) * AP + 2 + px];

  if ((dx & 3) == 0) {
    // vector path: displaced float4 stays aligned & validity is all-or-none
    const int sx = px - dx;             // multiple of 4
    const bool sxok = (unsigned)sx < (unsigned)W;
#pragma unroll
    for (int i = 0; i < 4; i++) {
      const int sy = fy + i * 16 - dy;
      float4 v = make_float4(0.f, 0.f, 0.f, 0.f);
      if (sxok && (unsigned)sy < (unsigned)H)
        v = __ldcs(reinterpret_cast<const float4*>(&src[sy * W + sx]));
      float* d = dstA + i * 16 * AP;    // col 2+4k: 8B-aligned -> STS.64 x2
      *reinterpret_cast<float2*>(d + 0) = make_float2(v.x, v.y);
      *reinterpret_cast<float2*>(d + 2) = make_float2(v.z, v.w);
    }
  } else {
    // generic scalar path (not taken for this problem's offset grid)
#pragma unroll
    for (int i = 0; i < 4; i++) {
      const int sy = fy + i * 16 - dy;
      const bool syok = (unsigned)sy < (unsigned)H;
#pragma unroll
      for (int u = 0; u < 4; u++) {
        const int sx = px + u - dx;
        float v = 0.f;
        if (syok && (unsigned)sx < (unsigned)W) v = __ldcs(&src[sy * W + sx]);
        dstA[i * 16 * AP + u] = v;
      }
    }
  }
  __syncthreads();                      // single barrier

  // --- per-thread output tile coordinates (4 wide x 4 tall) ---
  const int txi = tid & 15;             // 16 x-tiles of width 4
  const int tyi = tid >> 4;             // 16 y-tiles of height 4
  const int x0 = txi * 4;
  const int y0 = tyi * 4;
  float* __restrict__ dst = out + (size_t)plane * (H * W);

  // --- liveness: does this tile's input window touch any valid pixel? ---
  // valid displaced cols: [max(0,dx), min(W-1, W-1+dx)]; rows analogous.
  // tile input window: cols [x0-2, x0+5], rows [y0-2, y0+5].
  {
    const int cx0 = dx > 0 ? dx : 0;
    const int cx1 = dx < 0 ? (W - 1 + dx) : (W - 1);
    const int cy0 = dy > 0 ? dy : 0;
    const int cy1 = dy < 0 ? (H - 1 + dy) : (H - 1);
    const bool live = (x0 + 5 >= cx0) & (x0 - 2 <= cx1) &
                      (y0 + 5 >= cy0) & (y0 - 2 <= cy1);
    if (!live) {                        // entire tile is exactly zero
      const float4 z = make_float4(0.f, 0.f, 0.f, 0.f);
#pragma unroll
      for (int o = 0; o < 4; o++)
        __stcs(reinterpret_cast<float4*>(&dst[(y0 + o) * W + x0]), z);
      return;                           // no more barriers follow
    }
  }

  const float wx0 = swx[0], wx1 = swx[1], wx2 = swx[2], wx3 = swx[3], wx4 = swx[4];
  float wy[5];
#pragma unroll
  for (int i = 0; i < 5; i++) wy[i] = swy[i];

  // --- separable conv, 4x4 outputs per thread, register row-sliding ---
  float acc[4][4];
#pragma unroll
  for (int o = 0; o < 4; o++)
#pragma unroll
    for (int u = 0; u < 4; u++) acc[o][u] = 0.f;

#pragma unroll
  for (int r = 0; r < 8; r++) {         // 8 h-rows feed 4 output rows
    const float* row = &A[(y0 + r) * AP + x0];
    float4 a0 = *reinterpret_cast<const float4*>(row);
    float4 a1 = *reinterpret_cast<const float4*>(row + 4);
    float a[8] = {a0.x, a0.y, a0.z, a0.w, a1.x, a1.y, a1.z, a1.w};
    float h[4];
#pragma unroll
    for (int u = 0; u < 4; u++)
      h[u] = wx0 * a[u] + wx1 * a[u + 1] + wx2 * a[u + 2]
           + wx3 * a[u + 3] + wx4 * a[u + 4];
#pragma unroll
    for (int o = 0; o < 4; o++) {
      int i = r - o;                    // compile-time pruned
      if (i >= 0 && i < 5) {
        float wv = wy[i];
#pragma unroll
        for (int u = 0; u < 4; u++) acc[o][u] += wv * h[u];
      }
    }
  }

#pragma unroll
  for (int o = 0; o < 4; o++) {
    float4 v = make_float4(acc[o][0], acc[o][1], acc[o][2], acc[o][3]);
    __stcs(reinterpret_cast<float4*>(&dst[(y0 + o) * W + x0]), v);
  }
}

extern "C" void kernel_launch(void* const* d_in, const int* in_sizes, int n_in,
                              void* d_out, int out_size) {
  const float* x = (const float*)d_in[0];
  const float* offset = (const float*)d_in[1];
  float* out = (float*)d_out;
  displace_gauss_kernel<<<B * C, 256>>>(x, offset, out);
}